// round 5
// baseline (speedup 1.0000x reference)
#include <cuda_runtime.h>

#define NB 32
#define CI 64
#define LT 300
#define V  25
#define VP 26
#define KD 192

typedef unsigned long long ull;

// scratch: xwin[n][m][c][26]; v=25 pad column never written -> stays 0 (zero-init)
__device__ float g_xwin[(size_t)NB * LT * CI * VP];

__device__ __forceinline__ ull pack2(float lo, float hi){
    ull r; asm("mov.b64 %0,{%1,%2};" : "=l"(r) : "f"(lo), "f"(hi)); return r;
}
__device__ __forceinline__ void unpack2(ull v, float& lo, float& hi){
    asm("mov.b64 {%0,%1},%2;" : "=f"(lo), "=f"(hi) : "l"(v));
}
__device__ __forceinline__ ull ffma2(ull a, ull b, ull c){
    ull d; asm("fma.rn.f32x2 %0,%1,%2,%3;" : "=l"(d) : "l"(a), "l"(b), "l"(c)); return d;
}

// ---------- kernel 1: 9-tap causal window sum, register running-sum stream ----------
#define WCG 8
#define WLQ 75
#define WTH (WCG * V)

__global__ __launch_bounds__(WTH) void win_kernel(const float* __restrict__ x){
    const int b  = blockIdx.x;
    const int q  = b & 3;
    const int cg = (b >> 2) & 7;
    const int n  = b >> 5;
    const int t  = threadIdx.x;
    const int cl = t / V;
    const int v  = t - cl * V;
    const int c  = cg * WCG + cl;
    const int l0 = q * WLQ;

    const float* xp = x + ((size_t)(n * CI + c) * LT) * V + v;
    float* op = g_xwin + ((size_t)n * LT * CI + c) * VP + v;

    float ring[9];
    #pragma unroll
    for (int j = 0; j < 9; j++) ring[j] = 0.f;
    float s = 0.f;

    #pragma unroll 1
    for (int base = 0; base < 90; base += 9) {
        #pragma unroll
        for (int j = 0; j < 9; j++) {
            int l = l0 - 8 + base + j;
            float nv = (l >= 0 && l < LT) ? xp[(size_t)l * V] : 0.f;
            s += nv - ring[j];
            ring[j] = nv;
            if (l >= l0 && l < l0 + WLQ)
                op[(size_t)l * CI * VP] = s;
        }
    }
}

// ---------- kernel 2: fused contraction + BN + ReLU + residual ----------
// TPB=384, MT=2, 2 blocks/SM. Phase1: 4k x 4vp quarters. Phase2: 2co x 4wp, 256 threads.
#define TPB 384
#define MAIN_SMEM (75*16*8 + 2*CI*VP*4 + 2*KD*VP*4 + 2*CI*4)   // 63360 B

__global__ __launch_bounds__(TPB, 2) void main_kernel(
    const float* __restrict__ x,
    const float* __restrict__ A,
    const float* __restrict__ W,
    const float* __restrict__ gamma,
    const float* __restrict__ beta,
    const float* __restrict__ mean,
    const float* __restrict__ var,
    float* __restrict__ out)
{
    extern __shared__ ull smem[];
    ull*   As  = smem;                       // [75][16] packed w-pairs (13..15 zero)
    float* xwf = (float*)(As + 75*16);       // [2][64][26]
    float* ysm = xwf + 2*CI*VP;              // [2][192][26]
    float* bnA = ysm + 2*KD*VP;              // [64]
    float* bnB = bnA + CI;                   // [64]

    const int tid = threadIdx.x;
    const int n   = blockIdx.x / (LT/2);
    const int m0  = (blockIdx.x % (LT/2)) * 2;

    if (tid < CI){
        float inv = gamma[tid] * rsqrtf(var[tid] + 1e-3f);
        bnA[tid] = inv;
        bnB[tid] = beta[tid] - mean[tid]*inv;
    }
    for (int i = tid; i < 75*16; i += TPB){
        int pv = i >> 4, wp = i & 15;
        ull val = 0;
        if (wp < 13){
            float a0 = A[pv*V + 2*wp];
            float a1 = (wp < 12) ? A[pv*V + 2*wp + 1] : 0.f;
            val = pack2(a0, a1);
        }
        As[i] = val;
    }
    {
        const float4* src = (const float4*)(g_xwin + (size_t)(n*LT + m0)*CI*VP);
        float4* dst = (float4*)xwf;
        for (int i = tid; i < (2*CI*VP)/4; i += TPB) dst[i] = src[i];
    }
    __syncthreads();

    // ---- phase 1: y[k,:] = sum_c xw[c,:]*W[c,k]; 4 k-rows x 4 v-pairs per thread ----
    // v-quarters at pair offsets {0,3,6,9}; pairs 3,6,9 computed twice (identical) -> benign dup stores
    {
        const int mslot = tid / 192;
        const int s     = tid - mslot*192;
        const int kg    = s >> 2;
        const int vq    = s & 3;
        const int k0    = kg * 4;
        const int voff  = vq * 3;
        const ull* xr = (const ull*)(xwf + mslot*CI*VP);

        ull acc[4][4];
        #pragma unroll
        for (int i = 0; i < 4; i++)
            #pragma unroll
            for (int vp = 0; vp < 4; vp++) acc[i][vp] = 0;

        #pragma unroll 4
        for (int c = 0; c < CI; c++){
            float4 w = __ldg((const float4*)(W + c*KD + k0));
            ull w0 = pack2(w.x, w.x), w1 = pack2(w.y, w.y);
            ull w2 = pack2(w.z, w.z), w3 = pack2(w.w, w.w);
            const ull* xc = xr + c*13 + voff;
            #pragma unroll
            for (int vp = 0; vp < 4; vp++){
                ull xv = xc[vp];
                acc[0][vp] = ffma2(w0, xv, acc[0][vp]);
                acc[1][vp] = ffma2(w1, xv, acc[1][vp]);
                acc[2][vp] = ffma2(w2, xv, acc[2][vp]);
                acc[3][vp] = ffma2(w3, xv, acc[3][vp]);
            }
        }
        #pragma unroll
        for (int i = 0; i < 4; i++){
            ull* yr = (ull*)(ysm) + (size_t)(mslot*KD + k0 + i)*13 + voff;
            #pragma unroll
            for (int vp = 0; vp < 4; vp++) yr[vp] = acc[i][vp];
        }
    }
    __syncthreads();

    // ---- phase 2: t[co,w] = sum_{p,v} y[co*3+p,v]*A[p,v,w]; 2co x 4wpairs ----
    if (tid < 256){
        const int mslot = tid >> 7;
        const int s2    = tid & 127;
        const int cog   = s2 >> 2;      // 32 groups of 2 co
        const int wg    = s2 & 3;
        const int co0   = cog * 2;

        ull tac[2][4];
        #pragma unroll
        for (int i = 0; i < 2; i++)
            #pragma unroll
            for (int j = 0; j < 4; j++) tac[i][j] = 0;

        const float* yb = ysm + (size_t)mslot*KD*VP;
        #pragma unroll
        for (int p = 0; p < 3; p++){
            const ull* Ab = As + (p*V)*16 + wg*4;
            const float* yp = yb + (size_t)(co0*3 + p)*VP;
            #pragma unroll 3
            for (int v2 = 0; v2 < 12; v2++){
                int v = 2*v2;
                ull a00 = Ab[(v  )*16+0], a01 = Ab[(v  )*16+1], a02 = Ab[(v  )*16+2], a03 = Ab[(v  )*16+3];
                ull a10 = Ab[(v+1)*16+0], a11 = Ab[(v+1)*16+1], a12 = Ab[(v+1)*16+2], a13 = Ab[(v+1)*16+3];
                #pragma unroll
                for (int i = 0; i < 2; i++){
                    float y0, y1;
                    unpack2(*(const ull*)(yp + i*3*VP + v), y0, y1);
                    ull yy0 = pack2(y0, y0), yy1 = pack2(y1, y1);
                    tac[i][0] = ffma2(yy0, a00, tac[i][0]);
                    tac[i][1] = ffma2(yy0, a01, tac[i][1]);
                    tac[i][2] = ffma2(yy0, a02, tac[i][2]);
                    tac[i][3] = ffma2(yy0, a03, tac[i][3]);
                    tac[i][0] = ffma2(yy1, a10, tac[i][0]);
                    tac[i][1] = ffma2(yy1, a11, tac[i][1]);
                    tac[i][2] = ffma2(yy1, a12, tac[i][2]);
                    tac[i][3] = ffma2(yy1, a13, tac[i][3]);
                }
            }
            { // leftover v = 24
                ull a0 = Ab[24*16+0], a1 = Ab[24*16+1], a2 = Ab[24*16+2], a3 = Ab[24*16+3];
                #pragma unroll
                for (int i = 0; i < 2; i++){
                    float yv = yp[i*3*VP + 24];
                    ull yy = pack2(yv, yv);
                    tac[i][0] = ffma2(yy, a0, tac[i][0]);
                    tac[i][1] = ffma2(yy, a1, tac[i][1]);
                    tac[i][2] = ffma2(yy, a2, tac[i][2]);
                    tac[i][3] = ffma2(yy, a3, tac[i][3]);
                }
            }
        }

        const int m = m0 + mslot;
        #pragma unroll
        for (int i = 0; i < 2; i++){
            int co = co0 + i;
            float iv = bnA[co], bb = bnB[co];
            size_t base = ((size_t)(n*CI + co)*LT + m)*V;
            #pragma unroll
            for (int j = 0; j < 4; j++){
                int w0 = 2*(wg*4 + j);
                if (w0 >= V) break;
                float t0, t1; unpack2(tac[i][j], t0, t1);
                float r0 = fmaxf(fmaf(t0, iv, bb), 0.f);
                out[base + w0] = fmaxf(r0 + x[base + w0], 0.f);
                if (w0 + 1 < V){
                    float r1 = fmaxf(fmaf(t1, iv, bb), 0.f);
                    out[base + w0 + 1] = fmaxf(r1 + x[base + w0 + 1], 0.f);
                }
            }
        }
    }
}

extern "C" void kernel_launch(void* const* d_in, const int* in_sizes, int n_in,
                              void* d_out, int out_size) {
    const float* x     = (const float*)d_in[0];
    const float* A     = (const float*)d_in[1];
    const float* W     = (const float*)d_in[2];
    const float* gamma = (const float*)d_in[3];
    const float* beta  = (const float*)d_in[4];
    const float* mean  = (const float*)d_in[5];
    const float* var   = (const float*)d_in[6];
    float* out = (float*)d_out;

    win_kernel<<<NB * 8 * 4, WTH>>>(x);

    cudaFuncSetAttribute(main_kernel, cudaFuncAttributeMaxDynamicSharedMemorySize, MAIN_SMEM);
    main_kernel<<<NB * (LT/2), TPB, MAIN_SMEM>>>(x, A, W, gamma, beta, mean, var, out);
}

// round 6
// speedup vs baseline: 1.0921x; 1.0921x over previous
#include <cuda_runtime.h>

#define NB 32
#define CI 64
#define LT 300
#define V  25
#define VP 26
#define KD 192

typedef unsigned long long ull;

// scratch: xwin[n][m][c][26]; v=25 pad column never written -> stays 0 (zero-init)
__device__ float g_xwin[(size_t)NB * LT * CI * VP];

__device__ __forceinline__ ull pack2(float lo, float hi){
    ull r; asm("mov.b64 %0,{%1,%2};" : "=l"(r) : "f"(lo), "f"(hi)); return r;
}
__device__ __forceinline__ void unpack2(ull v, float& lo, float& hi){
    asm("mov.b64 {%0,%1},%2;" : "=f"(lo), "=f"(hi) : "l"(v));
}
__device__ __forceinline__ ull ffma2(ull a, ull b, ull c){
    ull d; asm("fma.rn.f32x2 %0,%1,%2,%3;" : "=l"(d) : "l"(a), "l"(b), "l"(c)); return d;
}

// ---------- kernel 1: 9-tap causal window sum, register running-sum stream ----------
#define WCG 8
#define WLQ 75
#define WTH (WCG * V)

__global__ __launch_bounds__(WTH) void win_kernel(const float* __restrict__ x){
    const int b  = blockIdx.x;
    const int q  = b & 3;
    const int cg = (b >> 2) & 7;
    const int n  = b >> 5;
    const int t  = threadIdx.x;
    const int cl = t / V;
    const int v  = t - cl * V;
    const int c  = cg * WCG + cl;
    const int l0 = q * WLQ;

    const float* xp = x + ((size_t)(n * CI + c) * LT) * V + v;
    float* op = g_xwin + ((size_t)n * LT * CI + c) * VP + v;

    float ring[9];
    #pragma unroll
    for (int j = 0; j < 9; j++) ring[j] = 0.f;
    float s = 0.f;

    #pragma unroll 1
    for (int base = 0; base < 90; base += 9) {
        #pragma unroll
        for (int j = 0; j < 9; j++) {
            int l = l0 - 8 + base + j;
            float nv = (l >= 0 && l < LT) ? xp[(size_t)l * V] : 0.f;
            s += nv - ring[j];
            ring[j] = nv;
            if (l >= l0 && l < l0 + WLQ)
                op[(size_t)l * CI * VP] = s;
        }
    }
}

// ---------- kernel 2: fused contraction + BN + ReLU + residual ----------
// TPB=192, MT=2, 3 blocks/SM. Phase1: 8k x 4vp. Phase2: 4co x 4wp with LDS.128 A loads.
#define TPB 192
#define MAIN_SMEM (75*16*8 + 2*CI*VP*4 + 2*KD*VP*4 + 2*CI*4)   // 63360 B

__global__ __launch_bounds__(TPB, 3) void main_kernel(
    const float* __restrict__ x,
    const float* __restrict__ A,
    const float* __restrict__ W,
    const float* __restrict__ gamma,
    const float* __restrict__ beta,
    const float* __restrict__ mean,
    const float* __restrict__ var,
    float* __restrict__ out)
{
    extern __shared__ ull smem[];
    ull*   As  = smem;                       // [75][16] packed w-pairs (13..15 zero)
    float* xwf = (float*)(As + 75*16);       // [2][64][26]
    float* ysm = xwf + 2*CI*VP;              // [2][192][26]
    float* bnA = ysm + 2*KD*VP;              // [64]
    float* bnB = bnA + CI;                   // [64]

    const int tid = threadIdx.x;
    const int n   = blockIdx.x / (LT/2);
    const int m0  = (blockIdx.x % (LT/2)) * 2;

    if (tid < CI){
        float inv = gamma[tid] * rsqrtf(var[tid] + 1e-3f);
        bnA[tid] = inv;
        bnB[tid] = beta[tid] - mean[tid]*inv;
    }
    for (int i = tid; i < 75*16; i += TPB){
        int pv = i >> 4, wp = i & 15;
        ull val = 0;
        if (wp < 13){
            float a0 = A[pv*V + 2*wp];
            float a1 = (wp < 12) ? A[pv*V + 2*wp + 1] : 0.f;
            val = pack2(a0, a1);
        }
        As[i] = val;
    }
    {
        const float4* src = (const float4*)(g_xwin + (size_t)(n*LT + m0)*CI*VP);
        float4* dst = (float4*)xwf;
        for (int i = tid; i < (2*CI*VP)/4; i += TPB) dst[i] = src[i];
    }
    __syncthreads();

    // ---- phase 1: y[k,:] = sum_c xw[c,:]*W[c,k]; 8 k-rows x 4 v-pairs per thread ----
    // v-quarters at pair offsets {0,3,6,9}; pairs 3,6,9 duplicated (identical) -> benign
    {
        const int mslot = tid / 96;
        const int s     = tid - mslot*96;
        const int kg    = s >> 2;          // 0..23
        const int vq    = s & 3;
        const int k0    = kg * 8;
        const int voff  = vq * 3;
        const ull* xr = (const ull*)(xwf + mslot*CI*VP);

        ull acc[8][4];
        #pragma unroll
        for (int i = 0; i < 8; i++)
            #pragma unroll
            for (int vp = 0; vp < 4; vp++) acc[i][vp] = 0;

        #pragma unroll 2
        for (int c = 0; c < CI; c++){
            float4 wa = __ldg((const float4*)(W + c*KD + k0));
            float4 wb = __ldg((const float4*)(W + c*KD + k0 + 4));
            ull w0 = pack2(wa.x, wa.x), w1 = pack2(wa.y, wa.y);
            ull w2 = pack2(wa.z, wa.z), w3 = pack2(wa.w, wa.w);
            ull w4 = pack2(wb.x, wb.x), w5 = pack2(wb.y, wb.y);
            ull w6 = pack2(wb.z, wb.z), w7 = pack2(wb.w, wb.w);
            const ull* xc = xr + c*13 + voff;
            ull xv0 = xc[0], xv1 = xc[1], xv2 = xc[2], xv3 = xc[3];
            acc[0][0]=ffma2(w0,xv0,acc[0][0]); acc[0][1]=ffma2(w0,xv1,acc[0][1]);
            acc[0][2]=ffma2(w0,xv2,acc[0][2]); acc[0][3]=ffma2(w0,xv3,acc[0][3]);
            acc[1][0]=ffma2(w1,xv0,acc[1][0]); acc[1][1]=ffma2(w1,xv1,acc[1][1]);
            acc[1][2]=ffma2(w1,xv2,acc[1][2]); acc[1][3]=ffma2(w1,xv3,acc[1][3]);
            acc[2][0]=ffma2(w2,xv0,acc[2][0]); acc[2][1]=ffma2(w2,xv1,acc[2][1]);
            acc[2][2]=ffma2(w2,xv2,acc[2][2]); acc[2][3]=ffma2(w2,xv3,acc[2][3]);
            acc[3][0]=ffma2(w3,xv0,acc[3][0]); acc[3][1]=ffma2(w3,xv1,acc[3][1]);
            acc[3][2]=ffma2(w3,xv2,acc[3][2]); acc[3][3]=ffma2(w3,xv3,acc[3][3]);
            acc[4][0]=ffma2(w4,xv0,acc[4][0]); acc[4][1]=ffma2(w4,xv1,acc[4][1]);
            acc[4][2]=ffma2(w4,xv2,acc[4][2]); acc[4][3]=ffma2(w4,xv3,acc[4][3]);
            acc[5][0]=ffma2(w5,xv0,acc[5][0]); acc[5][1]=ffma2(w5,xv1,acc[5][1]);
            acc[5][2]=ffma2(w5,xv2,acc[5][2]); acc[5][3]=ffma2(w5,xv3,acc[5][3]);
            acc[6][0]=ffma2(w6,xv0,acc[6][0]); acc[6][1]=ffma2(w6,xv1,acc[6][1]);
            acc[6][2]=ffma2(w6,xv2,acc[6][2]); acc[6][3]=ffma2(w6,xv3,acc[6][3]);
            acc[7][0]=ffma2(w7,xv0,acc[7][0]); acc[7][1]=ffma2(w7,xv1,acc[7][1]);
            acc[7][2]=ffma2(w7,xv2,acc[7][2]); acc[7][3]=ffma2(w7,xv3,acc[7][3]);
        }
        #pragma unroll
        for (int i = 0; i < 8; i++){
            ull* yr = (ull*)(ysm) + (size_t)(mslot*KD + k0 + i)*13 + voff;
            #pragma unroll
            for (int vp = 0; vp < 4; vp++) yr[vp] = acc[i][vp];
        }
    }
    __syncthreads();

    // ---- phase 2: t[co,w] = sum_{p,v} y[co*3+p,v]*A[p,v,w]; 4co x 4wpairs, A via LDS.128 ----
    if (tid < 128){
        const int mslot = tid >> 6;
        const int s2    = tid & 63;
        const int cog   = s2 >> 2;      // 16 groups of 4 co
        const int wg    = s2 & 3;
        const int co0   = cog * 4;

        ull tac[4][4];
        #pragma unroll
        for (int i = 0; i < 4; i++)
            #pragma unroll
            for (int j = 0; j < 4; j++) tac[i][j] = 0;

        const float* yb = ysm + (size_t)mslot*KD*VP;
        #pragma unroll
        for (int p = 0; p < 3; p++){
            const ull* Ab = As + (p*V)*16 + wg*4;
            const float* yp = yb + (size_t)(co0*3 + p)*VP;
            #pragma unroll 3
            for (int v2 = 0; v2 < 12; v2++){
                int v = 2*v2;
                ulonglong2 aA0 = *(const ulonglong2*)(Ab + (v  )*16);
                ulonglong2 aB0 = *(const ulonglong2*)(Ab + (v  )*16 + 2);
                ulonglong2 aA1 = *(const ulonglong2*)(Ab + (v+1)*16);
                ulonglong2 aB1 = *(const ulonglong2*)(Ab + (v+1)*16 + 2);
                #pragma unroll
                for (int i = 0; i < 4; i++){
                    float y0, y1;
                    unpack2(*(const ull*)(yp + i*3*VP + v), y0, y1);
                    ull yy0 = pack2(y0, y0), yy1 = pack2(y1, y1);
                    tac[i][0] = ffma2(yy0, aA0.x, tac[i][0]);
                    tac[i][1] = ffma2(yy0, aA0.y, tac[i][1]);
                    tac[i][2] = ffma2(yy0, aB0.x, tac[i][2]);
                    tac[i][3] = ffma2(yy0, aB0.y, tac[i][3]);
                    tac[i][0] = ffma2(yy1, aA1.x, tac[i][0]);
                    tac[i][1] = ffma2(yy1, aA1.y, tac[i][1]);
                    tac[i][2] = ffma2(yy1, aB1.x, tac[i][2]);
                    tac[i][3] = ffma2(yy1, aB1.y, tac[i][3]);
                }
            }
            { // leftover v = 24
                ulonglong2 aA = *(const ulonglong2*)(Ab + 24*16);
                ulonglong2 aB = *(const ulonglong2*)(Ab + 24*16 + 2);
                #pragma unroll
                for (int i = 0; i < 4; i++){
                    float yv = yp[i*3*VP + 24];
                    ull yy = pack2(yv, yv);
                    tac[i][0] = ffma2(yy, aA.x, tac[i][0]);
                    tac[i][1] = ffma2(yy, aA.y, tac[i][1]);
                    tac[i][2] = ffma2(yy, aB.x, tac[i][2]);
                    tac[i][3] = ffma2(yy, aB.y, tac[i][3]);
                }
            }
        }

        const int m = m0 + mslot;
        #pragma unroll
        for (int i = 0; i < 4; i++){
            int co = co0 + i;
            float iv = bnA[co], bb = bnB[co];
            size_t base = ((size_t)(n*CI + co)*LT + m)*V;
            #pragma unroll
            for (int j = 0; j < 4; j++){
                int w0 = 2*(wg*4 + j);
                if (w0 >= V) break;
                float t0, t1; unpack2(tac[i][j], t0, t1);
                float r0 = fmaxf(fmaf(t0, iv, bb), 0.f);
                out[base + w0] = fmaxf(r0 + x[base + w0], 0.f);
                if (w0 + 1 < V){
                    float r1 = fmaxf(fmaf(t1, iv, bb), 0.f);
                    out[base + w0 + 1] = fmaxf(r1 + x[base + w0 + 1], 0.f);
                }
            }
        }
    }
}

extern "C" void kernel_launch(void* const* d_in, const int* in_sizes, int n_in,
                              void* d_out, int out_size) {
    const float* x     = (const float*)d_in[0];
    const float* A     = (const float*)d_in[1];
    const float* W     = (const float*)d_in[2];
    const float* gamma = (const float*)d_in[3];
    const float* beta  = (const float*)d_in[4];
    const float* mean  = (const float*)d_in[5];
    const float* var   = (const float*)d_in[6];
    float* out = (float*)d_out;

    win_kernel<<<NB * 8 * 4, WTH>>>(x);

    cudaFuncSetAttribute(main_kernel, cudaFuncAttributeMaxDynamicSharedMemorySize, MAIN_SMEM);
    main_kernel<<<NB * (LT/2), TPB, MAIN_SMEM>>>(x, A, W, gamma, beta, mean, var, out);
}